// round 6
// baseline (speedup 1.0000x reference)
#include <cuda_runtime.h>

#define NCLASS 128
#define NTHR   256
#define OCC    5
#define NBLK   (152 * OCC)   // 760 blocks, single wave at 5 blocks/SM
#define UNROLL 8

// Global scratch — zero-initialized at module load; the finishing block
// re-zeros after consuming so every graph replay starts from a clean state.
__device__ float        g_colsum[NCLASS];
__device__ unsigned int g_counts[NCLASS];
__device__ float        g_picked;
__device__ unsigned int g_done;

// Packed f32x2 add (sm_103a dual-issue fp32 pipe).
__device__ __forceinline__ void add_f32x2(unsigned long long& acc,
                                          unsigned long long v) {
    asm("add.rn.f32x2 %0, %1, %2;" : "=l"(acc) : "l"(acc), "l"(v));
}
__device__ __forceinline__ unsigned long long pack_f32x2(float lo, float hi) {
    unsigned long long r;
    asm("mov.b64 %0, {%1, %2};" : "=l"(r) : "f"(lo), "f"(hi));
    return r;
}
__device__ __forceinline__ void unpack_f32x2(unsigned long long v,
                                             float& lo, float& hi) {
    asm("mov.b64 {%0, %1}, %2;" : "=f"(lo), "=f"(hi) : "l"(v));
}

// One warp per row. Lane l owns columns [4l, 4l+3] via one float4 load.
// Each row is consumed immediately after its load (low live-register count);
// ptxas hoists loads up to the register budget, preserving MLP.
__global__ __launch_bounds__(NTHR, OCC) void loss_fused_kernel(
    const float* __restrict__ pred,
    const int*   __restrict__ tgt,
    float*       __restrict__ out,
    int n)
{
    __shared__ float        s_colsum[NCLASS];
    __shared__ unsigned int s_counts[NCLASS];
    __shared__ float        s_picked;
    __shared__ unsigned int s_last;
    __shared__ float        s_fin[5];   // 4 warp partials + picked copy

    const int tid  = threadIdx.x;
    const int lane = tid & 31;
    const int wrp  = tid >> 5;

    if (tid < NCLASS) { s_colsum[tid] = 0.0f; s_counts[tid] = 0u; }
    if (tid == 0) s_picked = 0.0f;
    __syncthreads();

    const int gwarp = blockIdx.x * (NTHR >> 5) + wrp;
    const int W     = NBLK * (NTHR >> 5);     // total warps (stride)

    unsigned long long acc01 = 0ull, acc23 = 0ull;  // packed f32x2 col sums
    float pick = 0.f;

    int r = gwarp;
    for (; r + (UNROLL - 1) * W < n; r += UNROLL * W) {
        #pragma unroll
        for (int j = 0; j < UNROLL; j++) {
            const int rj = r + j * W;
            const float4 v = __ldcs(reinterpret_cast<const float4*>(
                                 pred + (size_t)rj * NCLASS + lane * 4));
            const int t = tgt[rj];

            add_f32x2(acc01, pack_f32x2(__expf(v.x), __expf(v.y)));
            add_f32x2(acc23, pack_f32x2(__expf(v.z), __expf(v.w)));

            if ((t >> 2) == lane) {
                const int k = t & 3;
                pick += (k == 0) ? v.x : (k == 1) ? v.y
                      : (k == 2) ? v.z : v.w;
            }
            if (lane == j) atomicAdd(&s_counts[t], 1u);  // lane j handles row j
        }
    }
    // Tail
    for (; r < n; r += W) {
        const float4 v = __ldcs(reinterpret_cast<const float4*>(
                             pred + (size_t)r * NCLASS + lane * 4));
        const int t = tgt[r];
        add_f32x2(acc01, pack_f32x2(__expf(v.x), __expf(v.y)));
        add_f32x2(acc23, pack_f32x2(__expf(v.z), __expf(v.w)));
        if ((t >> 2) == lane) {
            const int k = t & 3;
            pick += (k == 0) ? v.x : (k == 1) ? v.y : (k == 2) ? v.z : v.w;
        }
        if (lane == 0) atomicAdd(&s_counts[t], 1u);
    }

    float a0, a1, a2, a3;
    unpack_f32x2(acc01, a0, a1);
    unpack_f32x2(acc23, a2, a3);

    // Warp-reduce picked sum.
    #pragma unroll
    for (int off = 16; off > 0; off >>= 1)
        pick += __shfl_xor_sync(0xFFFFFFFFu, pick, off);
    if (lane == 0) atomicAdd(&s_picked, pick);

    // Per-lane column partials -> shared (cross-warp combine).
    atomicAdd(&s_colsum[lane * 4 + 0], a0);
    atomicAdd(&s_colsum[lane * 4 + 1], a1);
    atomicAdd(&s_colsum[lane * 4 + 2], a2);
    atomicAdd(&s_colsum[lane * 4 + 3], a3);
    __syncthreads();

    // Flush block partials to global.
    if (tid < NCLASS) {
        atomicAdd(&g_colsum[tid], s_colsum[tid]);
        if (s_counts[tid]) atomicAdd(&g_counts[tid], s_counts[tid]);
    }
    if (tid == 0) atomicAdd(&g_picked, s_picked);

    // ---- inline finalize by the last block to flush ----
    __threadfence();
    if (tid == 0)
        s_last = (atomicAdd(&g_done, 1u) == (unsigned)(NBLK - 1)) ? 1u : 0u;
    __syncthreads();
    if (!s_last) return;
    __threadfence();   // acquire side: order scratch reads after counter obs

    float diff   = 0.0f;
    float picked = 0.0f;
    if (tid < NCLASS) {
        diff = fabsf((float)g_counts[tid] - g_colsum[tid]);
        if (tid == 0) picked = g_picked;
        // Re-zero scratch for next replay (this thread's reads are done).
        g_colsum[tid] = 0.0f;
        g_counts[tid] = 0u;
    }
    if (tid == 0) { s_fin[4] = picked; g_picked = 0.0f; g_done = 0u; }

    #pragma unroll
    for (int off = 16; off > 0; off >>= 1)
        diff += __shfl_xor_sync(0xFFFFFFFFu, diff, off);
    if (tid < NCLASS && lane == 0) s_fin[wrp] = diff;
    __syncthreads();

    if (tid == 0) {
        const float extra = (s_fin[0] + s_fin[1] + s_fin[2] + s_fin[3]) / (float)n;
        out[0] = -s_fin[4] / (float)n + extra;
    }
}

extern "C" void kernel_launch(void* const* d_in, const int* in_sizes, int n_in,
                              void* d_out, int out_size) {
    const float* pred = (const float*)d_in[0];
    const int*   tgt  = (const int*)d_in[1];
    float*       out  = (float*)d_out;
    const int n = in_sizes[1];  // number of rows / targets

    loss_fused_kernel<<<NBLK, NTHR>>>(pred, tgt, out, n);
}

// round 7
// speedup vs baseline: 1.3598x; 1.3598x over previous
#include <cuda_runtime.h>

#define NCLASS 128
#define NTHR   512
#define OCC    2
#define NBLK   (152 * OCC)   // 304 blocks, single wave, 32 warps/SM
#define UNROLL 8

// Global scratch — zero-initialized at module load; the finishing block
// re-zeros after consuming so every graph replay starts from a clean state.
__device__ float        g_colsum[NCLASS];
__device__ unsigned int g_counts[NCLASS];
__device__ float        g_picked;
__device__ unsigned int g_done;

// One warp per row. Lane l owns columns [4l, 4l+3] via one float4 load.
// Batched v[8] loads -> 8 LDG.128 in flight per thread (proven-fastest body).
__global__ __launch_bounds__(NTHR, OCC) void loss_fused_kernel(
    const float* __restrict__ pred,
    const int*   __restrict__ tgt,
    float*       __restrict__ out,
    int n)
{
    __shared__ float        s_colsum[NCLASS];
    __shared__ unsigned int s_counts[NCLASS];
    __shared__ float        s_picked;
    __shared__ unsigned int s_last;
    __shared__ float        s_fin[17];  // 16 warp partials + picked copy

    const int tid  = threadIdx.x;
    const int lane = tid & 31;
    const int wrp  = tid >> 5;

    if (tid < NCLASS) { s_colsum[tid] = 0.0f; s_counts[tid] = 0u; }
    if (tid == 0) s_picked = 0.0f;
    __syncthreads();

    const int gwarp = blockIdx.x * (NTHR >> 5) + wrp;
    const int W     = NBLK * (NTHR >> 5);     // total warps (stride)

    float a0 = 0.f, a1 = 0.f, a2 = 0.f, a3 = 0.f;
    float pick = 0.f;

    int r = gwarp;
    for (; r + (UNROLL - 1) * W < n; r += UNROLL * W) {
        // One parallel target load: lane j (j<8) fetches row j's target.
        int tmine = 0;
        if (lane < UNROLL) tmine = __ldcs(tgt + r + lane * W);

        float4 v[UNROLL];
        #pragma unroll
        for (int j = 0; j < UNROLL; j++) {
            v[j] = __ldcs(reinterpret_cast<const float4*>(
                       pred + (size_t)(r + j * W) * NCLASS + lane * 4));
        }

        // Histogram: lane j owns row j's target (no broadcast needed).
        if (lane < UNROLL) atomicAdd(&s_counts[tmine], 1u);

        #pragma unroll
        for (int j = 0; j < UNROLL; j++) {
            a0 += __expf(v[j].x); a1 += __expf(v[j].y);
            a2 += __expf(v[j].z); a3 += __expf(v[j].w);
            const int t = __shfl_sync(0xFFFFFFFFu, tmine, j);
            if ((t >> 2) == lane) {
                const int k = t & 3;
                pick += (k == 0) ? v[j].x : (k == 1) ? v[j].y
                      : (k == 2) ? v[j].z : v[j].w;
            }
        }
    }
    // Tail
    for (; r < n; r += W) {
        const float4 v = __ldcs(reinterpret_cast<const float4*>(
                             pred + (size_t)r * NCLASS + lane * 4));
        const int t = tgt[r];
        a0 += __expf(v.x); a1 += __expf(v.y); a2 += __expf(v.z); a3 += __expf(v.w);
        if ((t >> 2) == lane) {
            const int k = t & 3;
            pick += (k == 0) ? v.x : (k == 1) ? v.y : (k == 2) ? v.z : v.w;
        }
        if (lane == 0) atomicAdd(&s_counts[t], 1u);
    }

    // Warp-reduce picked sum.
    #pragma unroll
    for (int off = 16; off > 0; off >>= 1)
        pick += __shfl_xor_sync(0xFFFFFFFFu, pick, off);
    if (lane == 0) atomicAdd(&s_picked, pick);

    // Per-lane column partials -> shared (cross-warp combine).
    atomicAdd(&s_colsum[lane * 4 + 0], a0);
    atomicAdd(&s_colsum[lane * 4 + 1], a1);
    atomicAdd(&s_colsum[lane * 4 + 2], a2);
    atomicAdd(&s_colsum[lane * 4 + 3], a3);
    __syncthreads();

    // Flush block partials to global.
    if (tid < NCLASS) {
        atomicAdd(&g_colsum[tid], s_colsum[tid]);
        if (s_counts[tid]) atomicAdd(&g_counts[tid], s_counts[tid]);
    }
    if (tid == 0) atomicAdd(&g_picked, s_picked);

    // ---- inline finalize by the last block to flush ----
    __threadfence();
    if (tid == 0)
        s_last = (atomicAdd(&g_done, 1u) == (unsigned)(NBLK - 1)) ? 1u : 0u;
    __syncthreads();
    if (!s_last) return;
    __threadfence();   // acquire side: order scratch reads after counter obs

    float diff   = 0.0f;
    float picked = 0.0f;
    if (tid < NCLASS) {
        diff = fabsf((float)g_counts[tid] - g_colsum[tid]);
        if (tid == 0) picked = g_picked;
        // Re-zero scratch for next replay (this thread's reads are done).
        g_colsum[tid] = 0.0f;
        g_counts[tid] = 0u;
    }
    if (tid == 0) { s_fin[16] = picked; g_picked = 0.0f; g_done = 0u; }

    #pragma unroll
    for (int off = 16; off > 0; off >>= 1)
        diff += __shfl_xor_sync(0xFFFFFFFFu, diff, off);
    if (tid < NCLASS && lane == 0) s_fin[wrp] = diff;
    __syncthreads();

    if (tid == 0) {
        const float extra = (s_fin[0] + s_fin[1] + s_fin[2] + s_fin[3]) / (float)n;
        out[0] = -s_fin[16] / (float)n + extra;
    }
}

extern "C" void kernel_launch(void* const* d_in, const int* in_sizes, int n_in,
                              void* d_out, int out_size) {
    const float* pred = (const float*)d_in[0];
    const int*   tgt  = (const int*)d_in[1];
    float*       out  = (float*)d_out;
    const int n = in_sizes[1];  // number of rows / targets

    loss_fused_kernel<<<NBLK, NTHR>>>(pred, tgt, out, n);
}

// round 8
// speedup vs baseline: 1.3603x; 1.0004x over previous
#include <cuda_runtime.h>

#define NCLASS 128
#define NTHR   256
#define OCC    4
#define NBLK   (152 * OCC)   // 608 blocks, single wave, 32 warps/SM
#define UNROLL 8
#define WPB    (NTHR / 32)   // warps per block

// Global scratch — zero-initialized at module load; the finishing block
// re-zeros after consuming so every graph replay starts from a clean state.
__device__ float        g_colsum[NCLASS];
__device__ unsigned int g_counts[NCLASS];
__device__ float        g_picked;
__device__ unsigned int g_done;

// One warp per row. Lane l owns columns [4l, 4l+3] via one float4 load.
// Block-contiguous scheduling: block b streams a contiguous ~880KB row slice;
// warps interleave at stride 8 rows inside it (sliding ~32KB window per SM).
__global__ __launch_bounds__(NTHR, OCC) void loss_fused_kernel(
    const float* __restrict__ pred,
    const int*   __restrict__ tgt,
    float*       __restrict__ out,
    int n)
{
    __shared__ float        s_colsum[NCLASS];
    __shared__ unsigned int s_counts[NCLASS];
    __shared__ float        s_picked;
    __shared__ unsigned int s_last;
    __shared__ float        s_fin[WPB + 1];   // warp partials + picked copy

    const int tid  = threadIdx.x;
    const int lane = tid & 31;
    const int wrp  = tid >> 5;

    if (tid < NCLASS) { s_colsum[tid] = 0.0f; s_counts[tid] = 0u; }
    if (tid == 0) s_picked = 0.0f;
    __syncthreads();

    // Contiguous slice for this block.
    const int chunk = n / NBLK;
    const int rem   = n % NBLK;
    const int bid   = blockIdx.x;
    const int base  = bid * chunk + (bid < rem ? bid : rem);
    const int end   = base + chunk + (bid < rem ? 1 : 0);

    float a0 = 0.f, a1 = 0.f, a2 = 0.f, a3 = 0.f;
    float pick = 0.f;

    int r = base + wrp;
    for (; r + (UNROLL - 1) * WPB < end; r += UNROLL * WPB) {
        float4 v[UNROLL];
        int    t[UNROLL];
        #pragma unroll
        for (int j = 0; j < UNROLL; j++) {
            const int rj = r + j * WPB;
            v[j] = __ldcs(reinterpret_cast<const float4*>(
                       pred + (size_t)rj * NCLASS + lane * 4));
            t[j] = tgt[rj];
        }
        #pragma unroll
        for (int j = 0; j < UNROLL; j++) {
            a0 += __expf(v[j].x); a1 += __expf(v[j].y);
            a2 += __expf(v[j].z); a3 += __expf(v[j].w);
            if ((t[j] >> 2) == lane) {
                const int k = t[j] & 3;
                pick += (k == 0) ? v[j].x : (k == 1) ? v[j].y
                      : (k == 2) ? v[j].z : v[j].w;
            }
            if (lane == j) atomicAdd(&s_counts[t[j]], 1u);  // lane j handles row j
        }
    }
    // Tail
    for (; r < end; r += WPB) {
        const float4 v = __ldcs(reinterpret_cast<const float4*>(
                             pred + (size_t)r * NCLASS + lane * 4));
        const int t = tgt[r];
        a0 += __expf(v.x); a1 += __expf(v.y); a2 += __expf(v.z); a3 += __expf(v.w);
        if ((t >> 2) == lane) {
            const int k = t & 3;
            pick += (k == 0) ? v.x : (k == 1) ? v.y : (k == 2) ? v.z : v.w;
        }
        if (lane == 0) atomicAdd(&s_counts[t], 1u);
    }

    // Warp-reduce picked sum.
    #pragma unroll
    for (int off = 16; off > 0; off >>= 1)
        pick += __shfl_xor_sync(0xFFFFFFFFu, pick, off);
    if (lane == 0) atomicAdd(&s_picked, pick);

    // Per-lane column partials -> shared (cross-warp combine).
    atomicAdd(&s_colsum[lane * 4 + 0], a0);
    atomicAdd(&s_colsum[lane * 4 + 1], a1);
    atomicAdd(&s_colsum[lane * 4 + 2], a2);
    atomicAdd(&s_colsum[lane * 4 + 3], a3);
    __syncthreads();

    // Flush block partials to global.
    if (tid < NCLASS) {
        atomicAdd(&g_colsum[tid], s_colsum[tid]);
        if (s_counts[tid]) atomicAdd(&g_counts[tid], s_counts[tid]);
    }
    if (tid == 0) atomicAdd(&g_picked, s_picked);

    // ---- inline finalize by the last block to flush ----
    __threadfence();
    if (tid == 0)
        s_last = (atomicAdd(&g_done, 1u) == (unsigned)(NBLK - 1)) ? 1u : 0u;
    __syncthreads();
    if (!s_last) return;
    __threadfence();   // acquire side: order scratch reads after counter obs

    float diff   = 0.0f;
    float picked = 0.0f;
    if (tid < NCLASS) {
        diff = fabsf((float)g_counts[tid] - g_colsum[tid]);
        if (tid == 0) picked = g_picked;
        // Re-zero scratch for next replay (this thread's reads are done).
        g_colsum[tid] = 0.0f;
        g_counts[tid] = 0u;
    }
    if (tid == 0) { s_fin[WPB] = picked; g_picked = 0.0f; g_done = 0u; }

    #pragma unroll
    for (int off = 16; off > 0; off >>= 1)
        diff += __shfl_xor_sync(0xFFFFFFFFu, diff, off);
    if (tid < NCLASS && lane == 0) s_fin[wrp] = diff;
    __syncthreads();

    if (tid == 0) {
        const float extra = (s_fin[0] + s_fin[1] + s_fin[2] + s_fin[3]) / (float)n;
        out[0] = -s_fin[WPB] / (float)n + extra;
    }
}

extern "C" void kernel_launch(void* const* d_in, const int* in_sizes, int n_in,
                              void* d_out, int out_size) {
    const float* pred = (const float*)d_in[0];
    const int*   tgt  = (const int*)d_in[1];
    float*       out  = (float*)d_out;
    const int n = in_sizes[1];  // number of rows / targets

    loss_fused_kernel<<<NBLK, NTHR>>>(pred, tgt, out, n);
}